// round 4
// baseline (speedup 1.0000x reference)
#include <cuda_runtime.h>
#include <math.h>

#define B_ 64
#define S_ 512
#define I_ 256
#define H_ 1024
#define O_ 256

// Unified scratch layout [s][b][h]. pre written by GEMM, overwritten in place
// by hidden states during the recurrence.
__device__ float g_buf0[S_ * B_ * H_];
__device__ float g_buf1[S_ * B_ * H_];
// Per-(layer, t, bgroup, nchunk) completion counters. Monotonic within a
// launch, zeroed by zero_flags_k at the start of every launch.
// Target per flag = 128 (8 producer CTAs x 16 warps each).
__device__ int g_flags[2 * S_ * 4 * 4];

typedef unsigned long long u64;

__device__ __forceinline__ u64 pack2(float x, float y) {
    u64 r; asm("mov.b64 %0,{%1,%2};" : "=l"(r) : "f"(x), "f"(y)); return r;
}
__device__ __forceinline__ u64 fma2(u64 a, u64 b, u64 c) {
    u64 d; asm("fma.rn.f32x2 %0,%1,%2,%3;" : "=l"(d) : "l"(a), "l"(b), "l"(c)); return d;
}
__device__ __forceinline__ u64 add2(u64 a, u64 b) {
    u64 d; asm("add.rn.f32x2 %0,%1,%2;" : "=l"(d) : "l"(a), "l"(b)); return d;
}
__device__ __forceinline__ float2 unpk(u64 v) {
    float2 f; asm("mov.b64 {%0,%1},%2;" : "=f"(f.x), "=f"(f.y) : "l"(v)); return f;
}
__device__ __forceinline__ void cpasync16(float* sdst, const float* gsrc) {
    unsigned sa = (unsigned)__cvta_generic_to_shared(sdst);
    asm volatile("cp.async.cg.shared.global [%0], [%1], 16;" :: "r"(sa), "l"(gsrc));
}
__device__ __forceinline__ int ld_acq(const int* p) {
    int v; asm volatile("ld.acquire.gpu.global.b32 %0, [%1];" : "=r"(v) : "l"(p) : "memory");
    return v;
}
__device__ __forceinline__ void red_release(int* p) {
    asm volatile("red.release.gpu.global.add.s32 [%0], 1;" :: "l"(p) : "memory");
}

__global__ void zero_flags_k(int* f) { f[blockIdx.x * 1024 + threadIdx.x] = 0; }

// ---------------------------------------------------------------------------
// Tiled fp32 GEMM, f32x2 microkernel. C(row(b,s), n) = sum_k A(row,k)*W[n][k]+b
// 64 b (full batch) x 128 n tile, BK=32, 128 threads, 8x8 microtile.
// AROW=0: A row = b*S+s (x [b][s][k]). AROW=1: A row = s*64+b (buf [s][b][h]).
// CROW=0: C row = s*64+b, width H_ (buf). CROW=1: C row = b*S+s, width O_.
// ---------------------------------------------------------------------------
template <int K, int AROW, int CROW>
__global__ void __launch_bounds__(128) gemm_k(const float* __restrict__ A,
                                              const float* __restrict__ W,
                                              const float* __restrict__ b1,
                                              const float* __restrict__ b2,
                                              float* __restrict__ C) {
    __shared__ __align__(16) float sA[32][68];
    __shared__ __align__(16) float sB[32][132];

    const int s   = blockIdx.y;
    const int n0  = blockIdx.x * 128;
    const int tid = threadIdx.x;
    const int tm  = tid & 7;
    const int tn  = tid >> 3;

    u64 acc[8][4];
#pragma unroll
    for (int i = 0; i < 8; i++)
#pragma unroll
        for (int j = 0; j < 4; j++) acc[i][j] = 0ull;

    for (int kc = 0; kc < K; kc += 32) {
#pragma unroll
        for (int i = 0; i < 4; i++) {
            int v = tid + i * 128;
            int b = v >> 3, kq = v & 7;
            size_t row = AROW ? ((size_t)s * B_ + b) : ((size_t)b * S_ + s);
            float4 f = __ldg((const float4*)(A + row * K + kc + kq * 4));
            sA[kq * 4 + 0][b] = f.x;
            sA[kq * 4 + 1][b] = f.y;
            sA[kq * 4 + 2][b] = f.z;
            sA[kq * 4 + 3][b] = f.w;
        }
#pragma unroll
        for (int i = 0; i < 8; i++) {
            int v = tid + i * 128;
            int n = v >> 3, kq = v & 7;
            float4 f = __ldg((const float4*)(W + (size_t)(n0 + n) * K + kc + kq * 4));
            sB[kq * 4 + 0][n] = f.x;
            sB[kq * 4 + 1][n] = f.y;
            sB[kq * 4 + 2][n] = f.z;
            sB[kq * 4 + 3][n] = f.w;
        }
        __syncthreads();
#pragma unroll
        for (int k = 0; k < 32; k++) {
            float4 a0 = *(const float4*)&sA[k][tm * 8];
            float4 a1 = *(const float4*)&sA[k][tm * 8 + 4];
            ulonglong2 w01 = *(const ulonglong2*)&sB[k][tn * 8];
            ulonglong2 w23 = *(const ulonglong2*)&sB[k][tn * 8 + 4];
            float av[8] = {a0.x, a0.y, a0.z, a0.w, a1.x, a1.y, a1.z, a1.w};
#pragma unroll
            for (int i = 0; i < 8; i++) {
                u64 ai = pack2(av[i], av[i]);
                acc[i][0] = fma2(ai, w01.x, acc[i][0]);
                acc[i][1] = fma2(ai, w01.y, acc[i][1]);
                acc[i][2] = fma2(ai, w23.x, acc[i][2]);
                acc[i][3] = fma2(ai, w23.y, acc[i][3]);
            }
        }
        __syncthreads();
    }

    float bias[8];
#pragma unroll
    for (int j8 = 0; j8 < 8; j8++) {
        int n = n0 + tn * 8 + j8;
        bias[j8] = b1[n] + (b2 ? b2[n] : 0.0f);
    }

    const int NC = CROW ? O_ : H_;
#pragma unroll
    for (int i = 0; i < 8; i++) {
        int b = tm * 8 + i;
        size_t row = CROW ? ((size_t)b * S_ + s) : ((size_t)s * B_ + b);
        float* Co = C + row * NC + n0 + tn * 8;
        float2 t0 = unpk(acc[i][0]), t1 = unpk(acc[i][1]);
        float2 t2 = unpk(acc[i][2]), t3 = unpk(acc[i][3]);
        *(float4*)Co       = make_float4(t0.x + bias[0], t0.y + bias[1],
                                         t1.x + bias[2], t1.y + bias[3]);
        *(float4*)(Co + 4) = make_float4(t2.x + bias[4], t2.y + bias[5],
                                         t3.x + bias[6], t3.y + bias[7]);
    }
}

// ---------------------------------------------------------------------------
// Recurrence: grid 128 = 32 n-groups x 4 b-groups. CTA owns 32 n x 16 b.
// 512 threads = 16 warps: warp = kg*4 + ng4. Quad kg (4 warps, threads
// kg*128..+127) owns k-chunk [kg*256, kg*256+256):
//   poll flag(t-1, bg, kg) -> cp.async its 16KB of h_{t-1} -> compute partial.
// Partials double-buffered in smem by step parity; ONE __syncthreads/step.
// Finalize spread over all 16 warps (warp w handles n-pair P=w, 16 b);
// each warp releases +1 to flag(t, bg, n0>>8); consumer target = 128.
// ---------------------------------------------------------------------------
#define SW_F  (H_ * 32)          // 32768 floats (128 KB)
#define SH_ROW 1028              // 1024 + 4 pad
#define SH_F  (16 * SH_ROW)      // 16448 floats
#define RED_STRIDE 1088          // u64 per parity buffer: 4*16*17

__global__ void __launch_bounds__(512) rnn_layer_kernel(const float* __restrict__ Whh,
                                                        float* __restrict__ buf,
                                                        int* __restrict__ flags) {
    extern __shared__ __align__(16) float smem[];
    float* sW = smem;            // [k][32]
    float* sH = smem + SW_F;     // [16][1028]
    u64*  red = (u64*)(sH + SH_F);   // [2][kg][P][17]

    const int tid  = threadIdx.x;
    const int warp = tid >> 5, lane = tid & 31;
    const int ng4  = warp & 3;
    const int kg   = warp >> 2;
    const int bb   = lane & 15;
    const int kh   = lane >> 4;
    const int bg   = blockIdx.x & 3;
    const int n0   = (blockIdx.x >> 2) * 32;
    const int b0   = bg * 16;
    const int nloc = ng4 * 8;
    const int kbase = kg * 256 + kh * 128;
    const int mychunk = n0 >> 8;       // chunk this CTA produces into
    const int gtid = tid & 127;        // id within kg quad

    // Load W slice: sW[k][j] = Whh[n0+j][k]
#pragma unroll
    for (int i = 0; i < 16; i++) {
        int v = tid + i * 512;          // 0..8191 float4s
        int j = v >> 8, k4 = v & 255;
        float4 f = __ldg((const float4*)(Whh + (size_t)(n0 + j) * H_ + k4 * 4));
        sW[(k4 * 4 + 0) * 32 + j] = f.x;
        sW[(k4 * 4 + 1) * 32 + j] = f.y;
        sW[(k4 * 4 + 2) * 32 + j] = f.z;
        sW[(k4 * 4 + 3) * 32 + j] = f.w;
    }
    __syncthreads();

    // t = 0: h_0 = tanh(pre_0); warp w handles n-pair P=w over 16 b
    if (lane < 16) {
        float* addr = buf + ((size_t)(b0 + lane)) * H_ + n0 + warp * 2;
        float2 v = unpk(*(const u64*)addr);
        *(u64*)addr = pack2(tanhf(v.x), tanhf(v.y));
    }
    __syncwarp();
    if (lane == 0) red_release(&flags[0 * 16 + bg * 4 + mychunk]);

    for (int t = 1; t < S_; t++) {
        u64* redw = red + (t & 1) * RED_STRIDE;

        // Wait for this quad's k-chunk producers (8 CTAs x 16 warps = 128)
        {
            const int* fl = &flags[(t - 1) * 16 + bg * 4 + kg];
            while (ld_acq(fl) < 128) { }
        }

        // Copy chunk kg: 16 rows x 256 floats (16 KB), by this quad
        {
            const float* src = buf + ((size_t)(t - 1) * B_ + b0) * H_ + kg * 256;
#pragma unroll
            for (int i = 0; i < 8; i++) {
                int v = gtid + i * 128;      // 0..1023 float4s
                int r = v >> 6, c = v & 63;
                cpasync16(&sH[r * SH_ROW + kg * 256 + c * 4], src + (size_t)r * H_ + c * 4);
            }
            asm volatile("cp.async.commit_group;");
            asm volatile("cp.async.wait_group 0;");
            asm volatile("bar.sync %0, 128;" :: "r"(1 + kg) : "memory");
        }

        // Compute: 8 n x 1 b x 128 k per lane
        u64 a0 = 0, a1 = 0, a2 = 0, a3 = 0;
        const float* hrow = sH + bb * SH_ROW + kbase;
#pragma unroll 8
        for (int k4 = 0; k4 < 32; k4++) {
            float4 hv = *(const float4*)(hrow + k4 * 4);
            const float* w = sW + (size_t)(kbase + k4 * 4) * 32 + nloc;
            {
                u64 ph = pack2(hv.x, hv.x);
                ulonglong2 wa = *(const ulonglong2*)w;
                ulonglong2 wb = *(const ulonglong2*)(w + 4);
                a0 = fma2(ph, wa.x, a0); a1 = fma2(ph, wa.y, a1);
                a2 = fma2(ph, wb.x, a2); a3 = fma2(ph, wb.y, a3);
            }
            {
                u64 ph = pack2(hv.y, hv.y);
                ulonglong2 wa = *(const ulonglong2*)(w + 32);
                ulonglong2 wb = *(const ulonglong2*)(w + 36);
                a0 = fma2(ph, wa.x, a0); a1 = fma2(ph, wa.y, a1);
                a2 = fma2(ph, wb.x, a2); a3 = fma2(ph, wb.y, a3);
            }
            {
                u64 ph = pack2(hv.z, hv.z);
                ulonglong2 wa = *(const ulonglong2*)(w + 64);
                ulonglong2 wb = *(const ulonglong2*)(w + 68);
                a0 = fma2(ph, wa.x, a0); a1 = fma2(ph, wa.y, a1);
                a2 = fma2(ph, wb.x, a2); a3 = fma2(ph, wb.y, a3);
            }
            {
                u64 ph = pack2(hv.w, hv.w);
                ulonglong2 wa = *(const ulonglong2*)(w + 96);
                ulonglong2 wb = *(const ulonglong2*)(w + 100);
                a0 = fma2(ph, wa.x, a0); a1 = fma2(ph, wa.y, a1);
                a2 = fma2(ph, wb.x, a2); a3 = fma2(ph, wb.y, a3);
            }
        }

        // Fold the two k-halves within the warp
        a0 = add2(a0, __shfl_xor_sync(0xffffffffu, a0, 16));
        a1 = add2(a1, __shfl_xor_sync(0xffffffffu, a1, 16));
        a2 = add2(a2, __shfl_xor_sync(0xffffffffu, a2, 16));
        a3 = add2(a3, __shfl_xor_sync(0xffffffffu, a3, 16));

        if (kh == 0) {
            int P0 = ng4 * 4;
            redw[kg * 272 + (P0 + 0) * 17 + bb] = a0;
            redw[kg * 272 + (P0 + 1) * 17 + bb] = a1;
            redw[kg * 272 + (P0 + 2) * 17 + bb] = a2;
            redw[kg * 272 + (P0 + 3) * 17 + bb] = a3;
        }
        __syncthreads();   // red[t&1] complete; sH reads of this step complete

        // Finalize: warp w handles n-pair P=w over all 16 b, then release
        if (lane < 16) {
            int P = warp, b = lane;
            u64 s01 = add2(redw[0 * 272 + P * 17 + b], redw[1 * 272 + P * 17 + b]);
            u64 s23 = add2(redw[2 * 272 + P * 17 + b], redw[3 * 272 + P * 17 + b]);
            u64 s = add2(s01, s23);
            float* addr = buf + ((size_t)t * B_ + b0 + b) * H_ + n0 + P * 2;
            s = add2(s, *(const u64*)addr);
            float2 v = unpk(s);
            *(u64*)addr = pack2(tanhf(v.x), tanhf(v.y));
        }
        __syncwarp();
        if (lane == 0) red_release(&flags[t * 16 + bg * 4 + mychunk]);
    }
}

// ---------------------------------------------------------------------------

extern "C" void kernel_launch(void* const* d_in, const int* in_sizes, int n_in,
                              void* d_out, int out_size) {
    const float* x      = (const float*)d_in[0];
    const float* W_ih_0 = (const float*)d_in[1];
    const float* W_hh_0 = (const float*)d_in[2];
    const float* b_ih_0 = (const float*)d_in[3];
    const float* b_hh_0 = (const float*)d_in[4];
    const float* W_ih_1 = (const float*)d_in[5];
    const float* W_hh_1 = (const float*)d_in[6];
    const float* b_ih_1 = (const float*)d_in[7];
    const float* b_hh_1 = (const float*)d_in[8];
    const float* fc_w   = (const float*)d_in[9];
    const float* fc_b   = (const float*)d_in[10];
    float* out = (float*)d_out;

    float *buf0, *buf1;
    int* flags;
    cudaGetSymbolAddress((void**)&buf0, g_buf0);
    cudaGetSymbolAddress((void**)&buf1, g_buf1);
    cudaGetSymbolAddress((void**)&flags, g_flags);

    const int rnn_smem = (SW_F + SH_F) * 4 + 2 * RED_STRIDE * 8;   // 214272 B
    static bool attr_set = false;
    if (!attr_set) {
        cudaFuncSetAttribute(rnn_layer_kernel,
                             cudaFuncAttributeMaxDynamicSharedMemorySize, rnn_smem);
        attr_set = true;
    }

    zero_flags_k<<<16, 1024>>>(flags);
    // 1. pre0[s][b][h] = x @ W_ih_0^T + (b_ih_0 + b_hh_0)
    gemm_k<I_, 0, 0><<<dim3(H_ / 128, S_), 128>>>(x, W_ih_0, b_ih_0, b_hh_0, buf0);
    // 2. layer-0 recurrence (in place)
    rnn_layer_kernel<<<128, 512, rnn_smem>>>(W_hh_0, buf0, flags);
    // 3. pre1[s][b][h] = hs0 @ W_ih_1^T + (b_ih_1 + b_hh_1)
    gemm_k<H_, 1, 0><<<dim3(H_ / 128, S_), 128>>>(buf0, W_ih_1, b_ih_1, b_hh_1, buf1);
    // 4. layer-1 recurrence (in place)
    rnn_layer_kernel<<<128, 512, rnn_smem>>>(W_hh_1, buf1, flags + S_ * 16);
    // 5. out[b][s][o] = hs1 @ fc_w^T + fc_b
    gemm_k<H_, 1, 1><<<dim3(O_ / 128, S_), 128>>>(buf1, fc_w, fc_b, nullptr, out);
}

// round 5
// speedup vs baseline: 1.1578x; 1.1578x over previous
#include <cuda_runtime.h>
#include <math.h>

#define B_ 64
#define S_ 512
#define I_ 256
#define H_ 1024
#define O_ 256

// Unified scratch layout [s][b][h]. pre written by GEMM, overwritten in place
// by hidden states during the recurrence.
__device__ float g_buf0[S_ * B_ * H_];
__device__ float g_buf1[S_ * B_ * H_];
// Per-(layer, t, bgroup, nchunk) completion counters. Monotonic within a
// launch, zeroed by zero_flags_k each launch. Target per flag = 8 (the 8
// producer CTAs of that 256-wide n-chunk, one release per CTA).
__device__ int g_flags[2 * S_ * 4 * 4];

typedef unsigned long long u64;

__device__ __forceinline__ u64 pack2(float x, float y) {
    u64 r; asm("mov.b64 %0,{%1,%2};" : "=l"(r) : "f"(x), "f"(y)); return r;
}
__device__ __forceinline__ u64 fma2(u64 a, u64 b, u64 c) {
    u64 d; asm("fma.rn.f32x2 %0,%1,%2,%3;" : "=l"(d) : "l"(a), "l"(b), "l"(c)); return d;
}
__device__ __forceinline__ u64 add2(u64 a, u64 b) {
    u64 d; asm("add.rn.f32x2 %0,%1,%2;" : "=l"(d) : "l"(a), "l"(b)); return d;
}
__device__ __forceinline__ float2 unpk(u64 v) {
    float2 f; asm("mov.b64 {%0,%1},%2;" : "=f"(f.x), "=f"(f.y) : "l"(v)); return f;
}
__device__ __forceinline__ void cpasync16(float* sdst, const float* gsrc) {
    unsigned sa = (unsigned)__cvta_generic_to_shared(sdst);
    asm volatile("cp.async.cg.shared.global [%0], [%1], 16;" :: "r"(sa), "l"(gsrc));
}
__device__ __forceinline__ int ld_acq(const int* p) {
    int v; asm volatile("ld.acquire.gpu.global.b32 %0, [%1];" : "=r"(v) : "l"(p) : "memory");
    return v;
}
__device__ __forceinline__ void red_release(int* p) {
    asm volatile("red.release.gpu.global.add.s32 [%0], 1;" :: "l"(p) : "memory");
}

__global__ void zero_flags_k(int* f) { f[blockIdx.x * 1024 + threadIdx.x] = 0; }

// ---------------------------------------------------------------------------
// Tiled fp32 GEMM, f32x2 microkernel (unchanged from R3).
// ---------------------------------------------------------------------------
template <int K, int AROW, int CROW>
__global__ void __launch_bounds__(128) gemm_k(const float* __restrict__ A,
                                              const float* __restrict__ W,
                                              const float* __restrict__ b1,
                                              const float* __restrict__ b2,
                                              float* __restrict__ C) {
    __shared__ __align__(16) float sA[32][68];
    __shared__ __align__(16) float sB[32][132];

    const int s   = blockIdx.y;
    const int n0  = blockIdx.x * 128;
    const int tid = threadIdx.x;
    const int tm  = tid & 7;
    const int tn  = tid >> 3;

    u64 acc[8][4];
#pragma unroll
    for (int i = 0; i < 8; i++)
#pragma unroll
        for (int j = 0; j < 4; j++) acc[i][j] = 0ull;

    for (int kc = 0; kc < K; kc += 32) {
#pragma unroll
        for (int i = 0; i < 4; i++) {
            int v = tid + i * 128;
            int b = v >> 3, kq = v & 7;
            size_t row = AROW ? ((size_t)s * B_ + b) : ((size_t)b * S_ + s);
            float4 f = __ldg((const float4*)(A + row * K + kc + kq * 4));
            sA[kq * 4 + 0][b] = f.x;
            sA[kq * 4 + 1][b] = f.y;
            sA[kq * 4 + 2][b] = f.z;
            sA[kq * 4 + 3][b] = f.w;
        }
#pragma unroll
        for (int i = 0; i < 8; i++) {
            int v = tid + i * 128;
            int n = v >> 3, kq = v & 7;
            float4 f = __ldg((const float4*)(W + (size_t)(n0 + n) * K + kc + kq * 4));
            sB[kq * 4 + 0][n] = f.x;
            sB[kq * 4 + 1][n] = f.y;
            sB[kq * 4 + 2][n] = f.z;
            sB[kq * 4 + 3][n] = f.w;
        }
        __syncthreads();
#pragma unroll
        for (int k = 0; k < 32; k++) {
            float4 a0 = *(const float4*)&sA[k][tm * 8];
            float4 a1 = *(const float4*)&sA[k][tm * 8 + 4];
            ulonglong2 w01 = *(const ulonglong2*)&sB[k][tn * 8];
            ulonglong2 w23 = *(const ulonglong2*)&sB[k][tn * 8 + 4];
            float av[8] = {a0.x, a0.y, a0.z, a0.w, a1.x, a1.y, a1.z, a1.w};
#pragma unroll
            for (int i = 0; i < 8; i++) {
                u64 ai = pack2(av[i], av[i]);
                acc[i][0] = fma2(ai, w01.x, acc[i][0]);
                acc[i][1] = fma2(ai, w01.y, acc[i][1]);
                acc[i][2] = fma2(ai, w23.x, acc[i][2]);
                acc[i][3] = fma2(ai, w23.y, acc[i][3]);
            }
        }
        __syncthreads();
    }

    float bias[8];
#pragma unroll
    for (int j8 = 0; j8 < 8; j8++) {
        int n = n0 + tn * 8 + j8;
        bias[j8] = b1[n] + (b2 ? b2[n] : 0.0f);
    }

    const int NC = CROW ? O_ : H_;
#pragma unroll
    for (int i = 0; i < 8; i++) {
        int b = tm * 8 + i;
        size_t row = CROW ? ((size_t)b * S_ + s) : ((size_t)s * B_ + b);
        float* Co = C + row * NC + n0 + tn * 8;
        float2 t0 = unpk(acc[i][0]), t1 = unpk(acc[i][1]);
        float2 t2 = unpk(acc[i][2]), t3 = unpk(acc[i][3]);
        *(float4*)Co       = make_float4(t0.x + bias[0], t0.y + bias[1],
                                         t1.x + bias[2], t1.y + bias[3]);
        *(float4*)(Co + 4) = make_float4(t2.x + bias[4], t2.y + bias[5],
                                         t3.x + bias[6], t3.y + bias[7]);
    }
}

// ---------------------------------------------------------------------------
// Recurrence: grid 128 = 32 n-groups x 4 b-groups. CTA owns 32 n x 16 b.
// 512 threads = 16 warps: warp = kg*4 + ng4. Quad kg owns k-chunk
// [kg*256, kg*256+256).
// Per step t:
//   - prefetch pre_t tile (2KB) into smem (no dependency -> issued first)
//   - 1 thread/quad polls flag(t-1, bg, kg) [target 8], quad barrier
//   - quad copies its 16KB h chunk via cp.async, computes partials
//   - syncthreads; coalesced finalize: warp w = batch row, lanes = n;
//     reduce 4 partials + sPre, tanh, ONE 128B line store per warp
//   - syncthreads; tid0 releases flag(t, bg, mychunk)
// ---------------------------------------------------------------------------
#define SW_F  (H_ * 32)          // 32768 floats (128 KB)
#define SH_ROW 1028              // 1024 + 4 pad
#define SH_F  (16 * SH_ROW)      // 16448 floats
#define RED_U64 (4 * 16 * 17)    // [kg][P][b(16)+pad]

__global__ void __launch_bounds__(512) rnn_layer_kernel(const float* __restrict__ Whh,
                                                        float* __restrict__ buf,
                                                        int* __restrict__ flags) {
    extern __shared__ __align__(16) float smem[];
    float* sW   = smem;                  // [k][32]
    float* sH   = smem + SW_F;           // [16][1028]
    u64*   red  = (u64*)(sH + SH_F);     // [kg][P][17]
    float* sPre = (float*)(red + RED_U64);  // [16][32]

    const int tid  = threadIdx.x;
    const int warp = tid >> 5, lane = tid & 31;
    const int ng4  = warp & 3;
    const int kg   = warp >> 2;
    const int bb   = lane & 15;
    const int kh   = lane >> 4;
    const int bg   = blockIdx.x & 3;
    const int n0   = (blockIdx.x >> 2) * 32;
    const int b0   = bg * 16;
    const int nloc = ng4 * 8;
    const int kbase = kg * 256 + kh * 128;
    const int mychunk = n0 >> 8;
    const int gtid = tid & 127;          // id within kg quad

    // Load W slice: sW[k][j] = Whh[n0+j][k]
#pragma unroll
    for (int i = 0; i < 16; i++) {
        int v = tid + i * 512;           // 0..8191 float4s
        int j = v >> 8, k4 = v & 255;
        float4 f = __ldg((const float4*)(Whh + (size_t)(n0 + j) * H_ + k4 * 4));
        sW[(k4 * 4 + 0) * 32 + j] = f.x;
        sW[(k4 * 4 + 1) * 32 + j] = f.y;
        sW[(k4 * 4 + 2) * 32 + j] = f.z;
        sW[(k4 * 4 + 3) * 32 + j] = f.w;
    }

    // t = 0: h_0 = tanh(pre_0); warp = batch row, lanes = n (coalesced)
    if (lane < 16) {
        float* addr = buf + ((size_t)(b0 + warp)) * H_ + n0 + lane * 2;
        float2 v = unpk(*(const u64*)addr);
        *(u64*)addr = pack2(tanhf(v.x), tanhf(v.y));
    }
    __syncthreads();
    if (tid == 0) red_release(&flags[0 * 16 + bg * 4 + mychunk]);

    for (int t = 1; t < S_; t++) {
        // Prefetch pre_t tile (own exclusive tile; no producer dependency).
        // Quad kg copies rows kg*4..kg*4+3 (gtid<32: one float4 each).
        if (gtid < 32) {
            int r = kg * 4 + (gtid >> 3), c = (gtid & 7) * 4;
            cpasync16(&sPre[r * 32 + c],
                      buf + ((size_t)t * B_ + b0 + r) * H_ + n0 + c);
        }

        // Wait for this quad's k-chunk producers (8 CTAs, 1 release each)
        if (gtid == 0) {
            const int* fl = &flags[(t - 1) * 16 + bg * 4 + kg];
            while (ld_acq(fl) < 8) __nanosleep(32);
        }
        asm volatile("bar.sync %0, 128;" :: "r"(1 + kg) : "memory");

        // Copy chunk kg: 16 rows x 256 floats (16 KB), by this quad
        {
            const float* src = buf + ((size_t)(t - 1) * B_ + b0) * H_ + kg * 256;
#pragma unroll
            for (int i = 0; i < 8; i++) {
                int v = gtid + i * 128;      // 0..1023 float4s
                int r = v >> 6, c = v & 63;
                cpasync16(&sH[r * SH_ROW + kg * 256 + c * 4], src + (size_t)r * H_ + c * 4);
            }
            asm volatile("cp.async.wait_all;" ::: "memory");
            asm volatile("bar.sync %0, 128;" :: "r"(1 + kg) : "memory");
        }

        // Compute: 8 n x 1 b x 128 k per lane
        u64 a0 = 0, a1 = 0, a2 = 0, a3 = 0;
        const float* hrow = sH + bb * SH_ROW + kbase;
#pragma unroll 8
        for (int k4 = 0; k4 < 32; k4++) {
            float4 hv = *(const float4*)(hrow + k4 * 4);
            const float* w = sW + (size_t)(kbase + k4 * 4) * 32 + nloc;
            {
                u64 ph = pack2(hv.x, hv.x);
                ulonglong2 wa = *(const ulonglong2*)w;
                ulonglong2 wb = *(const ulonglong2*)(w + 4);
                a0 = fma2(ph, wa.x, a0); a1 = fma2(ph, wa.y, a1);
                a2 = fma2(ph, wb.x, a2); a3 = fma2(ph, wb.y, a3);
            }
            {
                u64 ph = pack2(hv.y, hv.y);
                ulonglong2 wa = *(const ulonglong2*)(w + 32);
                ulonglong2 wb = *(const ulonglong2*)(w + 36);
                a0 = fma2(ph, wa.x, a0); a1 = fma2(ph, wa.y, a1);
                a2 = fma2(ph, wb.x, a2); a3 = fma2(ph, wb.y, a3);
            }
            {
                u64 ph = pack2(hv.z, hv.z);
                ulonglong2 wa = *(const ulonglong2*)(w + 64);
                ulonglong2 wb = *(const ulonglong2*)(w + 68);
                a0 = fma2(ph, wa.x, a0); a1 = fma2(ph, wa.y, a1);
                a2 = fma2(ph, wb.x, a2); a3 = fma2(ph, wb.y, a3);
            }
            {
                u64 ph = pack2(hv.w, hv.w);
                ulonglong2 wa = *(const ulonglong2*)(w + 96);
                ulonglong2 wb = *(const ulonglong2*)(w + 100);
                a0 = fma2(ph, wa.x, a0); a1 = fma2(ph, wa.y, a1);
                a2 = fma2(ph, wb.x, a2); a3 = fma2(ph, wb.y, a3);
            }
        }

        // Fold the two k-halves within the warp
        a0 = add2(a0, __shfl_xor_sync(0xffffffffu, a0, 16));
        a1 = add2(a1, __shfl_xor_sync(0xffffffffu, a1, 16));
        a2 = add2(a2, __shfl_xor_sync(0xffffffffu, a2, 16));
        a3 = add2(a3, __shfl_xor_sync(0xffffffffu, a3, 16));

        if (kh == 0) {
            int P0 = ng4 * 4;
            red[kg * 272 + (P0 + 0) * 17 + bb] = a0;
            red[kg * 272 + (P0 + 1) * 17 + bb] = a1;
            red[kg * 272 + (P0 + 2) * 17 + bb] = a2;
            red[kg * 272 + (P0 + 3) * 17 + bb] = a3;
        }
        __syncthreads();

        // Finalize: warp w = batch row b, lane = n-pair P. Coalesced 128B store.
        if (lane < 16) {
            int b = warp, P = lane;
            u64 s01 = add2(red[0 * 272 + P * 17 + b], red[1 * 272 + P * 17 + b]);
            u64 s23 = add2(red[2 * 272 + P * 17 + b], red[3 * 272 + P * 17 + b]);
            u64 s = add2(s01, s23);
            s = add2(s, *(const u64*)&sPre[b * 32 + P * 2]);
            float2 v = unpk(s);
            *(u64*)(buf + ((size_t)t * B_ + b0 + b) * H_ + n0 + P * 2)
                = pack2(tanhf(v.x), tanhf(v.y));
        }
        __syncthreads();
        if (tid == 0) red_release(&flags[t * 16 + bg * 4 + mychunk]);
    }
}

// ---------------------------------------------------------------------------

extern "C" void kernel_launch(void* const* d_in, const int* in_sizes, int n_in,
                              void* d_out, int out_size) {
    const float* x      = (const float*)d_in[0];
    const float* W_ih_0 = (const float*)d_in[1];
    const float* W_hh_0 = (const float*)d_in[2];
    const float* b_ih_0 = (const float*)d_in[3];
    const float* b_hh_0 = (const float*)d_in[4];
    const float* W_ih_1 = (const float*)d_in[5];
    const float* W_hh_1 = (const float*)d_in[6];
    const float* b_ih_1 = (const float*)d_in[7];
    const float* b_hh_1 = (const float*)d_in[8];
    const float* fc_w   = (const float*)d_in[9];
    const float* fc_b   = (const float*)d_in[10];
    float* out = (float*)d_out;

    float *buf0, *buf1;
    int* flags;
    cudaGetSymbolAddress((void**)&buf0, g_buf0);
    cudaGetSymbolAddress((void**)&buf1, g_buf1);
    cudaGetSymbolAddress((void**)&flags, g_flags);

    const int rnn_smem = (SW_F + SH_F) * 4 + RED_U64 * 8 + 16 * 32 * 4;  // 207616 B
    static bool attr_set = false;
    if (!attr_set) {
        cudaFuncSetAttribute(rnn_layer_kernel,
                             cudaFuncAttributeMaxDynamicSharedMemorySize, rnn_smem);
        attr_set = true;
    }

    zero_flags_k<<<16, 1024>>>(flags);
    // 1. pre0[s][b][h] = x @ W_ih_0^T + (b_ih_0 + b_hh_0)
    gemm_k<I_, 0, 0><<<dim3(H_ / 128, S_), 128>>>(x, W_ih_0, b_ih_0, b_hh_0, buf0);
    // 2. layer-0 recurrence (in place)
    rnn_layer_kernel<<<128, 512, rnn_smem>>>(W_hh_0, buf0, flags);
    // 3. pre1[s][b][h] = hs0 @ W_ih_1^T + (b_ih_1 + b_hh_1)
    gemm_k<H_, 1, 0><<<dim3(H_ / 128, S_), 128>>>(buf0, W_ih_1, b_ih_1, b_hh_1, buf1);
    // 4. layer-1 recurrence (in place)
    rnn_layer_kernel<<<128, 512, rnn_smem>>>(W_hh_1, buf1, flags + S_ * 16);
    // 5. out[b][s][o] = hs1 @ fc_w^T + fc_b
    gemm_k<H_, 1, 1><<<dim3(O_ / 128, S_), 128>>>(buf1, fc_w, fc_b, nullptr, out);
}

// round 6
// speedup vs baseline: 1.2105x; 1.0455x over previous
#include <cuda_runtime.h>
#include <math.h>

#define B_ 64
#define S_ 512
#define I_ 256
#define H_ 1024
#define O_ 256

// Unified scratch layout [s][b][h]. pre written by GEMM, overwritten in place
// by hidden states during the recurrence.
__device__ float g_buf0[S_ * B_ * H_];
__device__ float g_buf1[S_ * B_ * H_];
// Per-(layer, t, bgroup, nchunk) completion counters. Monotonic within a
// launch, zeroed by zero_flags_k each launch. Target per flag = 128
// (8 producer CTAs x 16 warps, one release per warp).
__device__ int g_flags[2 * S_ * 4 * 4];

typedef unsigned long long u64;

__device__ __forceinline__ u64 pack2(float x, float y) {
    u64 r; asm("mov.b64 %0,{%1,%2};" : "=l"(r) : "f"(x), "f"(y)); return r;
}
__device__ __forceinline__ u64 fma2(u64 a, u64 b, u64 c) {
    u64 d; asm("fma.rn.f32x2 %0,%1,%2,%3;" : "=l"(d) : "l"(a), "l"(b), "l"(c)); return d;
}
__device__ __forceinline__ u64 add2(u64 a, u64 b) {
    u64 d; asm("add.rn.f32x2 %0,%1,%2;" : "=l"(d) : "l"(a), "l"(b)); return d;
}
__device__ __forceinline__ float2 unpk(u64 v) {
    float2 f; asm("mov.b64 {%0,%1},%2;" : "=f"(f.x), "=f"(f.y) : "l"(v)); return f;
}
__device__ __forceinline__ void cpasync16(float* sdst, const float* gsrc) {
    unsigned sa = (unsigned)__cvta_generic_to_shared(sdst);
    asm volatile("cp.async.cg.shared.global [%0], [%1], 16;" :: "r"(sa), "l"(gsrc));
}
__device__ __forceinline__ int ld_acq(const int* p) {
    int v; asm volatile("ld.acquire.gpu.global.b32 %0, [%1];" : "=r"(v) : "l"(p) : "memory");
    return v;
}
__device__ __forceinline__ void red_release(int* p) {
    asm volatile("red.release.gpu.global.add.s32 [%0], 1;" :: "l"(p) : "memory");
}

__global__ void zero_flags_k(int* f) { f[blockIdx.x * 1024 + threadIdx.x] = 0; }

// ---------------------------------------------------------------------------
// Tiled fp32 GEMM, f32x2 microkernel (unchanged).
// ---------------------------------------------------------------------------
template <int K, int AROW, int CROW>
__global__ void __launch_bounds__(128) gemm_k(const float* __restrict__ A,
                                              const float* __restrict__ W,
                                              const float* __restrict__ b1,
                                              const float* __restrict__ b2,
                                              float* __restrict__ C) {
    __shared__ __align__(16) float sA[32][68];
    __shared__ __align__(16) float sB[32][132];

    const int s   = blockIdx.y;
    const int n0  = blockIdx.x * 128;
    const int tid = threadIdx.x;
    const int tm  = tid & 7;
    const int tn  = tid >> 3;

    u64 acc[8][4];
#pragma unroll
    for (int i = 0; i < 8; i++)
#pragma unroll
        for (int j = 0; j < 4; j++) acc[i][j] = 0ull;

    for (int kc = 0; kc < K; kc += 32) {
#pragma unroll
        for (int i = 0; i < 4; i++) {
            int v = tid + i * 128;
            int b = v >> 3, kq = v & 7;
            size_t row = AROW ? ((size_t)s * B_ + b) : ((size_t)b * S_ + s);
            float4 f = __ldg((const float4*)(A + row * K + kc + kq * 4));
            sA[kq * 4 + 0][b] = f.x;
            sA[kq * 4 + 1][b] = f.y;
            sA[kq * 4 + 2][b] = f.z;
            sA[kq * 4 + 3][b] = f.w;
        }
#pragma unroll
        for (int i = 0; i < 8; i++) {
            int v = tid + i * 128;
            int n = v >> 3, kq = v & 7;
            float4 f = __ldg((const float4*)(W + (size_t)(n0 + n) * K + kc + kq * 4));
            sB[kq * 4 + 0][n] = f.x;
            sB[kq * 4 + 1][n] = f.y;
            sB[kq * 4 + 2][n] = f.z;
            sB[kq * 4 + 3][n] = f.w;
        }
        __syncthreads();
#pragma unroll
        for (int k = 0; k < 32; k++) {
            float4 a0 = *(const float4*)&sA[k][tm * 8];
            float4 a1 = *(const float4*)&sA[k][tm * 8 + 4];
            ulonglong2 w01 = *(const ulonglong2*)&sB[k][tn * 8];
            ulonglong2 w23 = *(const ulonglong2*)&sB[k][tn * 8 + 4];
            float av[8] = {a0.x, a0.y, a0.z, a0.w, a1.x, a1.y, a1.z, a1.w};
#pragma unroll
            for (int i = 0; i < 8; i++) {
                u64 ai = pack2(av[i], av[i]);
                acc[i][0] = fma2(ai, w01.x, acc[i][0]);
                acc[i][1] = fma2(ai, w01.y, acc[i][1]);
                acc[i][2] = fma2(ai, w23.x, acc[i][2]);
                acc[i][3] = fma2(ai, w23.y, acc[i][3]);
            }
        }
        __syncthreads();
    }

    float bias[8];
#pragma unroll
    for (int j8 = 0; j8 < 8; j8++) {
        int n = n0 + tn * 8 + j8;
        bias[j8] = b1[n] + (b2 ? b2[n] : 0.0f);
    }

    const int NC = CROW ? O_ : H_;
#pragma unroll
    for (int i = 0; i < 8; i++) {
        int b = tm * 8 + i;
        size_t row = CROW ? ((size_t)b * S_ + s) : ((size_t)s * B_ + b);
        float* Co = C + row * NC + n0 + tn * 8;
        float2 t0 = unpk(acc[i][0]), t1 = unpk(acc[i][1]);
        float2 t2 = unpk(acc[i][2]), t3 = unpk(acc[i][3]);
        *(float4*)Co       = make_float4(t0.x + bias[0], t0.y + bias[1],
                                         t1.x + bias[2], t1.y + bias[3]);
        *(float4*)(Co + 4) = make_float4(t2.x + bias[4], t2.y + bias[5],
                                         t3.x + bias[6], t3.y + bias[7]);
    }
}

// ---------------------------------------------------------------------------
// Recurrence: grid 128 = 32 n-groups x 4 b-groups. CTA: 32 n x 16 b.
// 512 threads = 16 warps: warp = kg*4 + ng4 (kg k-chunk of 256, ng4 8 n).
// Lane = q*8 + ks: q = b-quad (b = i*4+q), ks = 16B-interleaved k-slice.
// Per-lane tile: 4 b x 8 n x 32 k -> 96 LDS.128 + 512 fma2 per step.
// sW stored [k][32] with XOR chunk swizzle (chunk ^ ((k>>2)&7)) so the 8
// ks-lanes of a w load hit 8 distinct bank groups (conflict-free).
// k-slice partials folded by 3 shfl levels; red/sPre parity-buffered ->
// ONE __syncthreads per step; per-warp release after finalize store.
// ---------------------------------------------------------------------------
#define SW_F  (H_ * 32)          // 32768 floats (128 KB)
#define SH_ROW 1028              // 1024 + 4 pad
#define SH_F  (16 * SH_ROW)      // 16448 floats
#define RED_U64 1024             // per parity: [kg(4)][b(16)][P(16)]

__global__ void __launch_bounds__(512) rnn_layer_kernel(const float* __restrict__ Whh,
                                                        float* __restrict__ buf,
                                                        int* __restrict__ flags) {
    extern __shared__ __align__(16) float smem[];
    float* sW   = smem;                     // [k][32] swizzled
    float* sH   = smem + SW_F;              // [16][1028]
    u64*   red  = (u64*)(sH + SH_F);        // [2][4][16][16]
    float* sPre = (float*)(red + 2 * RED_U64);  // [2][16][32]

    const int tid  = threadIdx.x;
    const int warp = tid >> 5, lane = tid & 31;
    const int ng4  = warp & 3;
    const int kg   = warp >> 2;
    const int ks   = lane & 7;
    const int q    = lane >> 3;
    const int bg   = blockIdx.x & 3;
    const int n0   = (blockIdx.x >> 2) * 32;
    const int b0   = bg * 16;
    const int nloc = ng4 * 8;
    const int cj0  = ng4 * 2;
    const int ca   = ((cj0 ^ ks) << 2);     // swizzled word offset, chunk a
    const int cb   = ca ^ 4;                // chunk a+1 (cj0 even -> xor 1 on chunk)
    const int mychunk = n0 >> 8;
    const int gtid = tid & 127;             // id within kg quad

    // Load W slice with chunk swizzle: element (k, j) -> sW[k*32 + ((j>>2 ^ (k>>2)&7)<<2) + (j&3)]
#pragma unroll
    for (int i = 0; i < 16; i++) {
        int v = tid + i * 512;              // 0..8191 float4s (j, k4)
        int j = v >> 8, k4 = v & 255;
        float4 f = __ldg((const float4*)(Whh + (size_t)(n0 + j) * H_ + k4 * 4));
        int sw = (((j >> 2) ^ (k4 & 7)) << 2) + (j & 3);
        sW[(k4 * 4 + 0) * 32 + sw] = f.x;
        sW[(k4 * 4 + 1) * 32 + sw] = f.y;
        sW[(k4 * 4 + 2) * 32 + sw] = f.z;
        sW[(k4 * 4 + 3) * 32 + sw] = f.w;
    }

    // t = 0: h_0 = tanh(pre_0); warp = b row, lanes = n-pairs (coalesced)
    if (lane < 16) {
        float* addr = buf + ((size_t)(b0 + warp)) * H_ + n0 + lane * 2;
        float2 v = unpk(*(const u64*)addr);
        *(u64*)addr = pack2(tanhf(v.x), tanhf(v.y));
    }
    __syncwarp();
    if (lane == 0) red_release(&flags[0 * 16 + bg * 4 + mychunk]);
    __syncthreads();   // sW visible to all before t=1 compute

    // Per-lane h row pointers (b = i*4 + q), k-slice base ks*4 within chunk
    const float* hb0 = sH + (0 * 4 + q) * SH_ROW + kg * 256 + ks * 4;
    const float* hb1 = sH + (1 * 4 + q) * SH_ROW + kg * 256 + ks * 4;
    const float* hb2 = sH + (2 * 4 + q) * SH_ROW + kg * 256 + ks * 4;
    const float* hb3 = sH + (3 * 4 + q) * SH_ROW + kg * 256 + ks * 4;
    const float* wbase = sW + (size_t)(kg * 256 + ks * 4) * 32;

    for (int t = 1; t < S_; t++) {
        u64*   redw = red + (t & 1) * RED_U64;
        float* sPw  = sPre + (t & 1) * 512;

        // Prefetch pre_t tile (own exclusive tile, no dependency)
        if (gtid < 32) {
            int r = kg * 4 + (gtid >> 3), c = (gtid & 7) * 4;
            cpasync16(&sPw[r * 32 + c],
                      buf + ((size_t)t * B_ + b0 + r) * H_ + n0 + c);
        }

        // Wait for this quad's k-chunk producers (8 CTAs x 16 warps)
        if (gtid == 0) {
            const int* fl = &flags[(t - 1) * 16 + bg * 4 + kg];
            while (ld_acq(fl) < 128) { }
        }
        asm volatile("bar.sync %0, 128;" :: "r"(1 + kg) : "memory");

        // Copy chunk kg: 16 rows x 256 floats (16 KB), by this quad
        {
            const float* src = buf + ((size_t)(t - 1) * B_ + b0) * H_ + kg * 256;
#pragma unroll
            for (int i = 0; i < 8; i++) {
                int v = gtid + i * 128;      // 0..1023 float4s
                int r = v >> 6, c = v & 63;
                cpasync16(&sH[r * SH_ROW + kg * 256 + c * 4], src + (size_t)r * H_ + c * 4);
            }
            asm volatile("cp.async.wait_all;" ::: "memory");
            asm volatile("bar.sync %0, 128;" :: "r"(1 + kg) : "memory");
        }

        // Compute: 4 b x 8 n x 32 k per lane
        u64 acc[4][4];
#pragma unroll
        for (int i = 0; i < 4; i++)
#pragma unroll
            for (int j = 0; j < 4; j++) acc[i][j] = 0ull;

#pragma unroll
        for (int it = 0; it < 8; it++) {
            const int fo = it * 32;                 // float offset step
            float4 h0 = *(const float4*)(hb0 + fo);
            float4 h1 = *(const float4*)(hb1 + fo);
            float4 h2 = *(const float4*)(hb2 + fo);
            float4 h3 = *(const float4*)(hb3 + fo);
            const float* wr = wbase + (size_t)fo * 32;
#define DO_KK(KK, CMP)                                                      \
            {                                                               \
                ulonglong2 wa = *(const ulonglong2*)(wr + KK * 32 + ca);    \
                ulonglong2 wb = *(const ulonglong2*)(wr + KK * 32 + cb);    \
                u64 p0 = pack2(h0.CMP, h0.CMP);                             \
                u64 p1 = pack2(h1.CMP, h1.CMP);                             \
                u64 p2 = pack2(h2.CMP, h2.CMP);                             \
                u64 p3 = pack2(h3.CMP, h3.CMP);                             \
                acc[0][0] = fma2(p0, wa.x, acc[0][0]);                      \
                acc[0][1] = fma2(p0, wa.y, acc[0][1]);                      \
                acc[0][2] = fma2(p0, wb.x, acc[0][2]);                      \
                acc[0][3] = fma2(p0, wb.y, acc[0][3]);                      \
                acc[1][0] = fma2(p1, wa.x, acc[1][0]);                      \
                acc[1][1] = fma2(p1, wa.y, acc[1][1]);                      \
                acc[1][2] = fma2(p1, wb.x, acc[1][2]);                      \
                acc[1][3] = fma2(p1, wb.y, acc[1][3]);                      \
                acc[2][0] = fma2(p2, wa.x, acc[2][0]);                      \
                acc[2][1] = fma2(p2, wa.y, acc[2][1]);                      \
                acc[2][2] = fma2(p2, wb.x, acc[2][2]);                      \
                acc[2][3] = fma2(p2, wb.y, acc[2][3]);                      \
                acc[3][0] = fma2(p3, wa.x, acc[3][0]);                      \
                acc[3][1] = fma2(p3, wa.y, acc[3][1]);                      \
                acc[3][2] = fma2(p3, wb.x, acc[3][2]);                      \
                acc[3][3] = fma2(p3, wb.y, acc[3][3]);                      \
            }
            DO_KK(0, x)
            DO_KK(1, y)
            DO_KK(2, z)
            DO_KK(3, w)
#undef DO_KK
        }

        // Fold 8 k-slices (lane bits 0..2)
#pragma unroll
        for (int i = 0; i < 4; i++)
#pragma unroll
            for (int j = 0; j < 4; j++) {
                acc[i][j] = add2(acc[i][j], __shfl_xor_sync(0xffffffffu, acc[i][j], 1));
                acc[i][j] = add2(acc[i][j], __shfl_xor_sync(0xffffffffu, acc[i][j], 2));
                acc[i][j] = add2(acc[i][j], __shfl_xor_sync(0xffffffffu, acc[i][j], 4));
            }

        if (ks == 0) {
#pragma unroll
            for (int i = 0; i < 4; i++)
#pragma unroll
                for (int j = 0; j < 4; j++)
                    redw[(kg * 16 + (i * 4 + q)) * 16 + ng4 * 4 + j] = acc[i][j];
        }
        __syncthreads();

        // Finalize: warp = b row, lanes 0..15 = n-pairs; coalesced store
        if (lane < 16) {
            int b = warp, P = lane;
            u64 s01 = add2(redw[(0 * 16 + b) * 16 + P], redw[(1 * 16 + b) * 16 + P]);
            u64 s23 = add2(redw[(2 * 16 + b) * 16 + P], redw[(3 * 16 + b) * 16 + P]);
            u64 s = add2(s01, s23);
            s = add2(s, *(const u64*)&sPw[b * 32 + P * 2]);
            float2 v = unpk(s);
            *(u64*)(buf + ((size_t)t * B_ + b0 + b) * H_ + n0 + P * 2)
                = pack2(tanhf(v.x), tanhf(v.y));
        }
        __syncwarp();
        if (lane == 0) red_release(&flags[t * 16 + bg * 4 + mychunk]);
    }
}

// ---------------------------------------------------------------------------

extern "C" void kernel_launch(void* const* d_in, const int* in_sizes, int n_in,
                              void* d_out, int out_size) {
    const float* x      = (const float*)d_in[0];
    const float* W_ih_0 = (const float*)d_in[1];
    const float* W_hh_0 = (const float*)d_in[2];
    const float* b_ih_0 = (const float*)d_in[3];
    const float* b_hh_0 = (const float*)d_in[4];
    const float* W_ih_1 = (const float*)d_in[5];
    const float* W_hh_1 = (const float*)d_in[6];
    const float* b_ih_1 = (const float*)d_in[7];
    const float* b_hh_1 = (const float*)d_in[8];
    const float* fc_w   = (const float*)d_in[9];
    const float* fc_b   = (const float*)d_in[10];
    float* out = (float*)d_out;

    float *buf0, *buf1;
    int* flags;
    cudaGetSymbolAddress((void**)&buf0, g_buf0);
    cudaGetSymbolAddress((void**)&buf1, g_buf1);
    cudaGetSymbolAddress((void**)&flags, g_flags);

    const int rnn_smem = (SW_F + SH_F) * 4 + 2 * RED_U64 * 8 + 2 * 512 * 4;  // 217344 B
    static bool attr_set = false;
    if (!attr_set) {
        cudaFuncSetAttribute(rnn_layer_kernel,
                             cudaFuncAttributeMaxDynamicSharedMemorySize, rnn_smem);
        attr_set = true;
    }

    zero_flags_k<<<16, 1024>>>(flags);
    // 1. pre0[s][b][h] = x @ W_ih_0^T + (b_ih_0 + b_hh_0)
    gemm_k<I_, 0, 0><<<dim3(H_ / 128, S_), 128>>>(x, W_ih_0, b_ih_0, b_hh_0, buf0);
    // 2. layer-0 recurrence (in place)
    rnn_layer_kernel<<<128, 512, rnn_smem>>>(W_hh_0, buf0, flags);
    // 3. pre1[s][b][h] = hs0 @ W_ih_1^T + (b_ih_1 + b_hh_1)
    gemm_k<H_, 1, 0><<<dim3(H_ / 128, S_), 128>>>(buf0, W_ih_1, b_ih_1, b_hh_1, buf1);
    // 4. layer-1 recurrence (in place)
    rnn_layer_kernel<<<128, 512, rnn_smem>>>(W_hh_1, buf1, flags + S_ * 16);
    // 5. out[b][s][o] = hs1 @ fc_w^T + fc_b
    gemm_k<H_, 1, 1><<<dim3(O_ / 128, S_), 128>>>(buf1, fc_w, fc_b, nullptr, out);
}